// round 15
// baseline (speedup 1.0000x reference)
#include <cuda_runtime.h>
#include <cuda_bf16.h>
#include <cuda_fp16.h>
#include <cstdint>
#include <math.h>

#define BATCH 8192
#define EDIM  256
#define HDIM  50
#define N_INNER 31
#define N_LEAF  32

// ---------------------------------------------------------------------------
// Device scratch
// ---------------------------------------------------------------------------
__device__ float g_pR[N_INNER * BATCH];
__device__ float g_yleaf[N_LEAF * BATCH];

__device__ __half g_xh[BATCH * EDIM];      // x fp16 hi
__device__ __half g_xl[BATCH * EDIM];      // x fp16 lo
__device__ __half g_e0h[BATCH * EDIM];
__device__ __half g_e0l[BATCH * EDIM];
__device__ __half g_e1h[BATCH * EDIM];
__device__ __half g_e1l[BATCH * EDIM];
__device__ __half g_ef[BATCH * EDIM];      // final emb, fp16 single
// encoder weights transposed [4][N=256][K=256] fp16 single
__device__ __half g_wte[4 * 65536];
// leaf weights transposed [32][N=256][K=256] fp16 single
__device__ __half g_lwh[N_LEAF * 65536];
// inner W1 transposed [31][64][256] fp16 single, Ww transposed [31][256][64]
__device__ __half g_w1h[N_INNER * 64 * 256];
__device__ __half g_wwh[N_INNER * 256 * 64];

// ---------------------------------------------------------------------------
// Helpers
// ---------------------------------------------------------------------------
__device__ __forceinline__ uint32_t smem_u32(const void* p) {
    uint32_t a;
    asm("{ .reg .u64 t; cvta.to.shared.u64 t, %1; cvt.u32.u64 %0, t; }" : "=r"(a) : "l"(p));
    return a;
}
#define CP_ASYNC16(dst, src) \
    asm volatile("cp.async.cg.shared.global [%0], [%1], 16;" :: "r"(dst), "l"(src) : "memory")
#define CP_COMMIT() asm volatile("cp.async.commit_group;" ::: "memory")
#define CP_WAIT1()  asm volatile("cp.async.wait_group 1;" ::: "memory")
#define CP_WAIT0()  asm volatile("cp.async.wait_group 0;" ::: "memory")

#define LDSM4(r, addr) \
    asm volatile("ldmatrix.sync.aligned.m8n8.x4.shared.b16 {%0,%1,%2,%3}, [%4];" \
        : "=r"((r)[0]), "=r"((r)[1]), "=r"((r)[2]), "=r"((r)[3]) : "r"(addr))

__device__ __forceinline__ void mma_f16(float* c, const uint32_t* a, const uint32_t* b) {
    asm volatile(
        "mma.sync.aligned.m16n8k16.row.col.f32.f16.f16.f32 "
        "{%0,%1,%2,%3}, {%4,%5,%6,%7}, {%8,%9}, {%0,%1,%2,%3};"
        : "+f"(c[0]), "+f"(c[1]), "+f"(c[2]), "+f"(c[3])
        : "r"(a[0]), "r"(a[1]), "r"(a[2]), "r"(a[3]), "r"(b[0]), "r"(b[1]));
}

// fp16 hi/lo split of a pair of floats
__device__ __forceinline__ void split2h(float a, float b, uint32_t& hi, uint32_t& lo) {
    __half h0 = __float2half(a), h1 = __float2half(b);
    __half l0 = __float2half(a - __half2float(h0));
    __half l1 = __float2half(b - __half2float(h1));
    __half hh[2] = {h0, h1}, ll[2] = {l0, l1};
    hi = *(uint32_t*)hh;
    lo = *(uint32_t*)ll;
}

// ---------------------------------------------------------------------------
// Mega-prep. Regions by blockIdx.x:
// x split fp16 | W1 fp16 | Ww fp16 | zero yl |
// enc-W transpose fp16 (4x64) | leaf-W transpose fp16 (32x64)
// ---------------------------------------------------------------------------
#define PR_X   2048
#define PR_W1  (PR_X + 1984)
#define PR_WW  (PR_W1 + 1984)
#define PR_Z   (PR_WW + 256)
#define PR_WTE (PR_Z + 4 * 64)
#define PR_WTL (PR_WTE + 32 * 64)

__global__ __launch_bounds__(256) void prep_all_kernel(
    const float* __restrict__ x, __half* __restrict__ xh,
    __half* __restrict__ xl,
    const float* __restrict__ W1, __half* __restrict__ w1h,
    const float* __restrict__ Ww, __half* __restrict__ wwh,
    float* __restrict__ yl,
    const float* __restrict__ encW, __half* __restrict__ wte,
    const float* __restrict__ lfW, __half* __restrict__ lwh)
{
    const int bid = blockIdx.x;
    const int t = threadIdx.x;
    if (bid < PR_X) {
        int i = bid * 256 + t;
        float4 v = ((const float4*)x)[i];
        float f[4] = {v.x, v.y, v.z, v.w};
        __half h[4], l[4];
#pragma unroll
        for (int j = 0; j < 4; j++) {
            h[j] = __float2half(f[j]);
            l[j] = __float2half(f[j] - __half2float(h[j]));
        }
        *(uint2*)(xh + 4 * (size_t)i) = *(uint2*)h;
        *(uint2*)(xl + 4 * (size_t)i) = *(uint2*)l;
    } else if (bid < PR_W1) {
        int idx = (bid - PR_X) * 256 + t;
        int k = idx & 255, j = (idx >> 8) & 63, n = idx >> 14;
        float v = (j < HDIM) ? W1[((size_t)n * 256 + k) * HDIM + j] : 0.f;
        w1h[idx] = __float2half(v);
    } else if (bid < PR_WW) {
        int idx = (bid - PR_W1) * 256 + t;
        int j = idx & 63, d = (idx >> 6) & 255, n = idx >> 14;
        float v = (j < HDIM) ? Ww[((size_t)n * HDIM + j) * 256 + d] : 0.f;
        wwh[idx] = __float2half(v);
    } else if (bid < PR_Z) {
        int i = (bid - PR_WW) * 256 + t;
        ((float4*)yl)[i] = make_float4(0.f, 0.f, 0.f, 0.f);
    } else if (bid < PR_WTE) {
        __shared__ float tt[32][33];
        const int rel = bid - PR_Z;
        const int mat = rel >> 6;
        const int sub = rel & 63;
        const int nb = (sub & 7) * 32, kb = (sub >> 3) * 32;
        const int tx = t & 31, ty = t >> 5;
        const float* src = encW + (size_t)mat * 65536;
#pragma unroll
        for (int i = 0; i < 4; i++)
            tt[ty + 8 * i][tx] = src[(size_t)(kb + ty + 8 * i) * 256 + nb + tx];
        __syncthreads();
#pragma unroll
        for (int i = 0; i < 4; i++) {
            float v = tt[tx][ty + 8 * i];
            size_t idx = (size_t)mat * 65536 + (size_t)(nb + ty + 8 * i) * 256 + kb + tx;
            wte[idx] = __float2half(v);
        }
    } else {
        __shared__ float tt[32][33];
        const int rel = bid - PR_WTE;
        const int mat = rel >> 6;
        const int sub = rel & 63;
        const int nb = (sub & 7) * 32, kb = (sub >> 3) * 32;
        const int tx = t & 31, ty = t >> 5;
        const float* src = lfW + (size_t)mat * 65536;
#pragma unroll
        for (int i = 0; i < 4; i++)
            tt[ty + 8 * i][tx] = src[(size_t)(kb + ty + 8 * i) * 256 + nb + tx];
        __syncthreads();
#pragma unroll
        for (int i = 0; i < 4; i++) {
            float v = tt[tx][ty + 8 * i];
            size_t idx = (size_t)mat * 65536 + (size_t)(nb + ty + 8 * i) * 256 + kb + tx;
            lwh[idx] = __float2half(v);
        }
    }
}

// ---------------------------------------------------------------------------
// Encoder GEMM: fp16, activation hi/lo x weight single (2 MMA/k-step).
// M=64, N=64, 3-stage, 256 thr, grid 512 CTAs -> ~3.5 CTAs/SM available.
// Warps 2m x 4n (warp tile 32x16). occ 3 (regs ~60, smem 45KB x 3 = 135KB).
// MODE 0: emit fp16 hi/lo.  MODE 1 (L4): emit fp16 single.
// ---------------------------------------------------------------------------
#define E_AL 5120
#define E_B  10240
#define E_SZ 15360
#define ENC_SMEM (3 * E_SZ)

template <int MODE>
__global__ __launch_bounds__(256, 3) void enc_kernel(
    const __half* __restrict__ Ah, const __half* __restrict__ Al,
    const __half* __restrict__ B,
    const float* __restrict__ bias,
    __half* __restrict__ oh, __half* __restrict__ ol,
    __half* __restrict__ ef)
{
    extern __shared__ char smem[];
    const uint32_t sbase = smem_u32(smem);
    const int tid = threadIdx.x;
    const int lane = tid & 31, warp = tid >> 5;
    const int m0 = blockIdx.x * 64;
    const int n0 = blockIdx.y * 64;
    const int wm = (warp >> 2) * 32;   // {0,32}
    const int wn = (warp & 3) * 16;    // {0,16,32,48}

    float c[2][2][4];
#pragma unroll
    for (int mf = 0; mf < 2; mf++)
#pragma unroll
        for (int nf = 0; nf < 2; nf++)
#pragma unroll
            for (int q = 0; q < 4; q++) c[mf][nf][q] = 0.f;

    const int crow = tid >> 2;
    const int cu   = tid & 3;
    const int arow = (lane & 7) + ((lane >> 3) & 1) * 8;
    const int acol = (lane >> 4) * 8;
    const int brow = (lane & 7) + (lane >> 4) * 8;
    const int bcol = ((lane >> 3) & 1) * 8;

#define E_ISSUE(CI) do {                                                        \
    const int k0_ = (CI) * 32;                                                  \
    const uint32_t st_ = sbase + ((CI) % 3) * E_SZ;                             \
    const uint32_t da = st_ + crow * 80 + cu * 16;                              \
    const size_t ga = (size_t)(m0 + crow) * 256 + k0_ + cu * 8;                 \
    const size_t gb = (size_t)(n0 + crow) * 256 + k0_ + cu * 8;                 \
    CP_ASYNC16(da,         Ah + ga);                                            \
    CP_ASYNC16(da + E_AL,  Al + ga);                                            \
    CP_ASYNC16(st_ + E_B + crow * 80 + cu * 16, B + gb);                        \
    CP_COMMIT();                                                                \
} while (0)

    E_ISSUE(0);
    E_ISSUE(1);

#pragma unroll 1
    for (int ci = 0; ci < 8; ci++) {
        if (ci < 7) CP_WAIT1(); else CP_WAIT0();
        __syncthreads();
        if (ci < 6) E_ISSUE(ci + 2);

        const uint32_t st = sbase + (ci % 3) * E_SZ;
#pragma unroll
        for (int kk = 0; kk < 32; kk += 16) {
            uint32_t ah[2][4], al[2][4];
#pragma unroll
            for (int mf = 0; mf < 2; mf++) {
                uint32_t addr = st + (wm + mf * 16 + arow) * 80 + (kk + acol) * 2;
                LDSM4(ah[mf], addr);
                LDSM4(al[mf], addr + E_AL);
            }
            uint32_t r[4];
            LDSM4(r, st + E_B + (wn + brow) * 80 + (kk + bcol) * 2);
            uint32_t bf[2][2];
            bf[0][0] = r[0]; bf[0][1] = r[1];
            bf[1][0] = r[2]; bf[1][1] = r[3];
#pragma unroll
            for (int mf = 0; mf < 2; mf++)
#pragma unroll
                for (int nf = 0; nf < 2; nf++) {
                    mma_f16(c[mf][nf], ah[mf], bf[nf]);
                    mma_f16(c[mf][nf], al[mf], bf[nf]);
                }
        }
    }
#undef E_ISSUE

    const int erow = lane >> 2;
    const int ecol = (lane & 3) * 2;
#pragma unroll
    for (int mf = 0; mf < 2; mf++) {
        const int gr0 = m0 + wm + mf * 16 + erow;
#pragma unroll
        for (int nf = 0; nf < 2; nf++) {
            const int gc = n0 + wn + nf * 8 + ecol;
            float2 bb = *(const float2*)&bias[gc];
            float v00 = fmaxf(c[mf][nf][0] + bb.x, 0.f);
            float v01 = fmaxf(c[mf][nf][1] + bb.y, 0.f);
            float v10 = fmaxf(c[mf][nf][2] + bb.x, 0.f);
            float v11 = fmaxf(c[mf][nf][3] + bb.y, 0.f);
            const size_t i0 = (size_t)gr0 * 256 + gc;
            const size_t i1 = (size_t)(gr0 + 8) * 256 + gc;
            if (MODE == 0) {
                uint32_t h0, l0, h1, l1;
                split2h(v00, v01, h0, l0);
                split2h(v10, v11, h1, l1);
                *(uint32_t*)(oh + i0) = h0;
                *(uint32_t*)(oh + i1) = h1;
                *(uint32_t*)(ol + i0) = l0;
                *(uint32_t*)(ol + i1) = l1;
            } else {
                __half p0[2] = {__float2half(v00), __float2half(v01)};
                __half p1[2] = {__float2half(v10), __float2half(v11)};
                *(uint32_t*)(ef + i0) = *(uint32_t*)p0;
                *(uint32_t*)(ef + i1) = *(uint32_t*)p1;
            }
        }
    }
}

// ---------------------------------------------------------------------------
// TAIL kernel: inner (blockIdx.x < 31) + leaf (blockIdx.x >= 31).
// Pure fp16 single x single: 1 MMA per k-step. grid (63, 128), block 256.
// (Unchanged from round 12/13 — proven.)
// ---------------------------------------------------------------------------
#define IA_SZ  10240
#define IB_SZ  12288
#define IN_HF  36864
#define IN_RED 46080
#define IN_WBS 47616
#define IN_WBTS 47872
#define L_B   10240
#define L_STG 20480
#define L_SC  (3 * L_STG)
#define TAIL_SMEM (L_SC + 1024)

__global__ __launch_bounds__(256, 2) void tail_kernel(
    const __half* __restrict__ ef,
    const __half* __restrict__ w1h, const __half* __restrict__ wwh,
    const float* __restrict__ x, const float* __restrict__ b1,
    const float* __restrict__ bw, const float* __restrict__ Wb,
    const float* __restrict__ bb, const float* __restrict__ Wbt,
    const float* __restrict__ bbt, float* __restrict__ pR,
    const __half* __restrict__ Lwh,
    const float* __restrict__ lbias, const float* __restrict__ w2,
    float* __restrict__ yleaf)
{
    extern __shared__ char smem[];
    const uint32_t sb = smem_u32(smem);
    const int tid = threadIdx.x, lane = tid & 31, w = tid >> 5;

    const int arow = (lane & 7) + ((lane >> 3) & 1) * 8;
    const int acol = (lane >> 4) * 8;
    const int brow = (lane & 7) + (lane >> 4) * 8;
    const int bcol = ((lane >> 3) & 1) * 8;
    const int crow = tid >> 2, cu = tid & 3;

    if (blockIdx.x < N_INNER) {
        // ================= INNER path =================
        const int n = blockIdx.x, m0 = blockIdx.y * 64;

        float* sWb  = (float*)(smem + IN_WBS);
        float* sWbt = (float*)(smem + IN_WBTS);
        if (tid < HDIM)          sWb[tid] = Wb[n * HDIM + tid];
        else if (tid < 2 * HDIM) sWbt[tid - HDIM] = Wbt[n * HDIM + tid - HDIM];

        const __half* w1p = w1h + (size_t)n * 64 * 256;
        const __half* wwp = wwh + (size_t)n * 256 * 64;

#define IN_ISSUE(CI) do {                                           \
    const int k0_ = (CI) * 32;                                      \
    const uint32_t st_ = sb + ((CI) % 3) * IA_SZ;                   \
    const uint32_t d = st_ + crow * 80 + cu * 16;                   \
    const size_t ga = (size_t)(m0 + crow) * 256 + k0_ + cu * 8;     \
    const size_t gw = (size_t)crow * 256 + k0_ + cu * 8;            \
    CP_ASYNC16(d,        ef + ga);                                  \
    CP_ASYNC16(d + 5120, w1p + gw);                                 \
    CP_COMMIT();                                                    \
} while (0)

        const int wmA = (w >> 1) * 16, wnA = (w & 1) * 32;
        float accA[4][4];
#pragma unroll
        for (int i = 0; i < 4; i++)
#pragma unroll
            for (int q = 0; q < 4; q++) accA[i][q] = 0.f;

        IN_ISSUE(0);
        IN_ISSUE(1);

#pragma unroll 1
        for (int ci = 0; ci < 8; ci++) {
            if (ci < 7) CP_WAIT1(); else CP_WAIT0();
            __syncthreads();
            if (ci < 6) IN_ISSUE(ci + 2);

            const uint32_t st = sb + (ci % 3) * IA_SZ;
#pragma unroll
            for (int kk = 0; kk < 32; kk += 16) {
                uint32_t a[4];
                LDSM4(a, st + (wmA + arow) * 80 + (kk + acol) * 2);
                uint32_t bf[4][2];
#pragma unroll
                for (int g = 0; g < 2; g++) {
                    uint32_t r[4];
                    LDSM4(r, st + 5120 + (wnA + g * 16 + brow) * 80 + (kk + bcol) * 2);
                    bf[2 * g][0] = r[0]; bf[2 * g][1] = r[1];
                    bf[2 * g + 1][0] = r[2]; bf[2 * g + 1][1] = r[3];
                }
#pragma unroll
                for (int nf = 0; nf < 4; nf++)
                    mma_f16(accA[nf], a, bf[nf]);
            }
        }
#undef IN_ISSUE

        {
            const int r0 = wmA + (lane >> 2);
#pragma unroll
            for (int nf = 0; nf < 4; nf++) {
                const int col = wnA + nf * 8 + (lane & 3) * 2;
                const float bb0 = (col < HDIM)     ? b1[n * HDIM + col]     : 0.f;
                const float bb1 = (col + 1 < HDIM) ? b1[n * HDIM + col + 1] : 0.f;
                __half p0[2] = {__float2half(fmaxf(accA[nf][0] + bb0, 0.f)),
                                __float2half(fmaxf(accA[nf][1] + bb1, 0.f))};
                __half p1[2] = {__float2half(fmaxf(accA[nf][2] + bb0, 0.f)),
                                __float2half(fmaxf(accA[nf][3] + bb1, 0.f))};
                *(uint32_t*)(smem + IN_HF + r0 * 144 + col * 2) = *(uint32_t*)p0;
                *(uint32_t*)(smem + IN_HF + (r0 + 8) * 144 + col * 2) = *(uint32_t*)p1;
            }
        }
        __syncthreads();

#define IN_ISSUE_B(KK) do {                                         \
    const uint32_t st_ = sb + ((KK) % 3) * IB_SZ;                   \
    const uint32_t d = st_ + tid * 48;                              \
    const size_t g = (size_t)tid * 64 + (KK) * 16;                  \
    CP_ASYNC16(d,      wwp + g);                                    \
    CP_ASYNC16(d + 16, wwp + g + 8);                                \
    CP_COMMIT();                                                    \
} while (0)

        const int wmB = (w >> 1) * 16, wnB = (w & 1) * 128;
        float z[16][4];
#pragma unroll
        for (int nf = 0; nf < 16; nf++)
#pragma unroll
            for (int q = 0; q < 4; q++) z[nf][q] = 0.f;

        IN_ISSUE_B(0);
        IN_ISSUE_B(1);

#pragma unroll 1
        for (int kk = 0; kk < 4; kk++) {
            if (kk < 3) CP_WAIT1(); else CP_WAIT0();
            __syncthreads();
            if (kk < 2) IN_ISSUE_B(kk + 2);

            const uint32_t st = sb + (kk % 3) * IB_SZ;
            uint32_t a[4];
            LDSM4(a, sb + IN_HF + (wmB + arow) * 144 + (kk * 16 + acol) * 2);
#pragma unroll
            for (int g = 0; g < 8; g++) {
                uint32_t r[4];
                LDSM4(r, st + (wnB + g * 16 + brow) * 48 + bcol * 2);
                uint32_t b0[2] = {r[0], r[1]}, b1f[2] = {r[2], r[3]};
                mma_f16(z[2 * g],     a, b0);
                mma_f16(z[2 * g + 1], a, b1f);
            }
        }
#undef IN_ISSUE_B

        float* redmax = (float*)(smem + IN_RED);
        float* redse  = redmax + 128;
        float* redsx  = redse + 128;

        const int r0 = wmB + (lane >> 2), r1 = r0 + 8;
        float mx0 = -1e30f, mx1 = -1e30f;
#pragma unroll
        for (int nf = 0; nf < 16; nf++) {
            const int col = wnB + nf * 8 + (lane & 3) * 2;
            float2 bwv = *(const float2*)&bw[n * 256 + col];
            z[nf][0] += bwv.x; z[nf][1] += bwv.y;
            z[nf][2] += bwv.x; z[nf][3] += bwv.y;
            mx0 = fmaxf(mx0, fmaxf(z[nf][0], z[nf][1]));
            mx1 = fmaxf(mx1, fmaxf(z[nf][2], z[nf][3]));
        }
        mx0 = fmaxf(mx0, __shfl_xor_sync(0xffffffffu, mx0, 1));
        mx0 = fmaxf(mx0, __shfl_xor_sync(0xffffffffu, mx0, 2));
        mx1 = fmaxf(mx1, __shfl_xor_sync(0xffffffffu, mx1, 1));
        mx1 = fmaxf(mx1, __shfl_xor_sync(0xffffffffu, mx1, 2));
        if ((lane & 3) == 0) {
            redmax[(w & 1) * 64 + r0] = mx0;
            redmax[(w & 1) * 64 + r1] = mx1;
        }
        __syncthreads();
        mx0 = fmaxf(redmax[r0], redmax[64 + r0]);
        mx1 = fmaxf(redmax[r1], redmax[64 + r1]);

        float se0 = 0.f, sx0 = 0.f, se1 = 0.f, sx1 = 0.f;
        const float* x0 = x + (size_t)(m0 + r0) * 256;
        const float* x1 = x + (size_t)(m0 + r1) * 256;
#pragma unroll
        for (int nf = 0; nf < 16; nf++) {
            const int col = wnB + nf * 8 + (lane & 3) * 2;
            float2 xv0 = *(const float2*)&x0[col];
            float2 xv1 = *(const float2*)&x1[col];
            float e;
            e = __expf(z[nf][0] - mx0); se0 += e; sx0 = fmaf(e, xv0.x, sx0);
            e = __expf(z[nf][1] - mx0); se0 += e; sx0 = fmaf(e, xv0.y, sx0);
            e = __expf(z[nf][2] - mx1); se1 += e; sx1 = fmaf(e, xv1.x, sx1);
            e = __expf(z[nf][3] - mx1); se1 += e; sx1 = fmaf(e, xv1.y, sx1);
        }
#pragma unroll
        for (int off = 1; off <= 2; off <<= 1) {
            se0 += __shfl_xor_sync(0xffffffffu, se0, off);
            sx0 += __shfl_xor_sync(0xffffffffu, sx0, off);
            se1 += __shfl_xor_sync(0xffffffffu, se1, off);
            sx1 += __shfl_xor_sync(0xffffffffu, sx1, off);
        }
        if ((lane & 3) == 0) {
            redse[(w & 1) * 64 + r0] = se0; redse[(w & 1) * 64 + r1] = se1;
            redsx[(w & 1) * 64 + r0] = sx0; redsx[(w & 1) * 64 + r1] = sx1;
        }
        __syncthreads();

        if ((w & 1) == 0) {
            float pb0 = 0.f, pbt0 = 0.f, pb1 = 0.f, pbt1 = 0.f;
            for (int j = (lane & 3); j < HDIM; j += 4) {
                float h0 = __half2float(*(const __half*)(smem + IN_HF + r0 * 144 + j * 2));
                float h1 = __half2float(*(const __half*)(smem + IN_HF + r1 * 144 + j * 2));
                pb0  = fmaf(h0, sWb[j],  pb0);
                pbt0 = fmaf(h0, sWbt[j], pbt0);
                pb1  = fmaf(h1, sWb[j],  pb1);
                pbt1 = fmaf(h1, sWbt[j], pbt1);
            }
#pragma unroll
            for (int off = 1; off <= 2; off <<= 1) {
                pb0  += __shfl_xor_sync(0xffffffffu, pb0, off);
                pbt0 += __shfl_xor_sync(0xffffffffu, pbt0, off);
                pb1  += __shfl_xor_sync(0xffffffffu, pb1, off);
                pbt1 += __shfl_xor_sync(0xffffffffu, pbt1, off);
            }
            if ((lane & 3) == 0) {
                const float bbn = bb[n], bbtn = bbt[n];
                float seA = redse[r0] + redse[64 + r0];
                float sxA = redsx[r0] + redsx[64 + r0];
                float val = (pbt0 + bbtn) * (sxA / seA + pb0 + bbn);
                pR[(size_t)n * BATCH + m0 + r0] = 1.f / (1.f + __expf(-val));
                seA = redse[r1] + redse[64 + r1];
                sxA = redsx[r1] + redsx[64 + r1];
                val = (pbt1 + bbtn) * (sxA / seA + pb1 + bbn);
                pR[(size_t)n * BATCH + m0 + r1] = 1.f / (1.f + __expf(-val));
            }
        }
    } else {
        // ================= LEAF path =================
        const int mat = blockIdx.x - N_INNER;
        const int m0 = (blockIdx.y >> 1) * 128;
        const int n0 = (blockIdx.y & 1) * 128;
        const int wm = (w >> 1) * 32;
        const int wn = (w & 1) * 64;

        const __half* bp = Lwh + (size_t)mat * 65536;

        float* s_bias = (float*)(smem + L_SC);
        float* s_w2   = (float*)(smem + L_SC + 512);
        if (tid < 128) {
            s_bias[tid] = lbias[(size_t)mat * 256 + n0 + tid];
            s_w2[tid]   = w2[(size_t)mat * 256 + n0 + tid];
        }

        float c[2][8][4];
#pragma unroll
        for (int mf = 0; mf < 2; mf++)
#pragma unroll
            for (int nf = 0; nf < 8; nf++)
#pragma unroll
                for (int q = 0; q < 4; q++) c[mf][nf][q] = 0.f;

#define L_ISSUE(CI) do {                                                        \
    const int k0_ = (CI) * 32;                                                  \
    const uint32_t st_ = sb + ((CI) % 3) * L_STG;                               \
    const uint32_t d0 = st_ + crow * 80 + cu * 16;                              \
    const uint32_t d1 = st_ + (crow + 64) * 80 + cu * 16;                       \
    const size_t ga = (size_t)(m0 + crow) * 256 + k0_ + cu * 8;                 \
    const size_t gb = (size_t)(n0 + crow) * 256 + k0_ + cu * 8;                 \
    CP_ASYNC16(d0,        ef + ga);                                             \
    CP_ASYNC16(d1,        ef + ga + 64 * 256);                                  \
    CP_ASYNC16(d0 + L_B,  bp + gb);                                             \
    CP_ASYNC16(d1 + L_B,  bp + gb + 64 * 256);                                  \
    CP_COMMIT();                                                                \
} while (0)

        L_ISSUE(0);
        L_ISSUE(1);

#pragma unroll 1
        for (int ci = 0; ci < 8; ci++) {
            if (ci < 7) CP_WAIT1(); else CP_WAIT0();
            __syncthreads();
            if (ci < 6) L_ISSUE(ci + 2);

            const uint32_t st = sb + (ci % 3) * L_STG;
#pragma unroll
            for (int kk = 0; kk < 32; kk += 16) {
                uint32_t a[2][4];
#pragma unroll
                for (int mf = 0; mf < 2; mf++)
                    LDSM4(a[mf], st + (wm + mf * 16 + arow) * 80 + (kk + acol) * 2);
                uint32_t bf[8][2];
#pragma unroll
                for (int np = 0; np < 4; np++) {
                    uint32_t r[4];
                    LDSM4(r, st + L_B + (wn + np * 16 + brow) * 80 + (kk + bcol) * 2);
                    bf[2 * np][0] = r[0]; bf[2 * np][1] = r[1];
                    bf[2 * np + 1][0] = r[2]; bf[2 * np + 1][1] = r[3];
                }
#pragma unroll
                for (int mf = 0; mf < 2; mf++)
#pragma unroll
                    for (int nf = 0; nf < 8; nf++)
                        mma_f16(c[mf][nf], a[mf], bf[nf]);
            }
        }
#undef L_ISSUE

        const int erow = lane >> 2;
        const int ecol = (lane & 3) * 2;
        float part[2][2] = {{0.f, 0.f}, {0.f, 0.f}};
#pragma unroll
        for (int mf = 0; mf < 2; mf++)
#pragma unroll
            for (int nf = 0; nf < 8; nf++) {
                const int lc = wn + nf * 8 + ecol;
                const float b0s = s_bias[lc], b1s = s_bias[lc + 1];
                const float w0 = s_w2[lc], w1 = s_w2[lc + 1];
                part[mf][0] = fmaf(fmaxf(c[mf][nf][0] + b0s, 0.f), w0, part[mf][0]);
                part[mf][0] = fmaf(fmaxf(c[mf][nf][1] + b1s, 0.f), w1, part[mf][0]);
                part[mf][1] = fmaf(fmaxf(c[mf][nf][2] + b0s, 0.f), w0, part[mf][1]);
                part[mf][1] = fmaf(fmaxf(c[mf][nf][3] + b1s, 0.f), w1, part[mf][1]);
            }
#pragma unroll
        for (int mf = 0; mf < 2; mf++)
#pragma unroll
            for (int h = 0; h < 2; h++) {
                part[mf][h] += __shfl_xor_sync(0xffffffffu, part[mf][h], 1);
                part[mf][h] += __shfl_xor_sync(0xffffffffu, part[mf][h], 2);
            }
        if ((lane & 3) == 0) {
#pragma unroll
            for (int mf = 0; mf < 2; mf++)
#pragma unroll
                for (int h = 0; h < 2; h++) {
                    const int row = m0 + wm + mf * 16 + h * 8 + erow;
                    atomicAdd(&yleaf[(size_t)mat * BATCH + row], part[mf][h]);
                }
        }
    }
}

// ---------------------------------------------------------------------------
// Combine
// ---------------------------------------------------------------------------
__global__ __launch_bounds__(256) void combine_kernel(
    const float* __restrict__ pR, const float* __restrict__ yl,
    const float* __restrict__ b2, float* __restrict__ out)
{
    const int b = blockIdx.x * 256 + threadIdx.x;
    float p[N_INNER];
#pragma unroll
    for (int i = 0; i < N_INNER; i++) p[i] = pR[(size_t)i * BATCH + b];

    float prob[N_LEAF];
    prob[0] = 1.f;
#pragma unroll
    for (int lev = 0; lev < 5; lev++) {
        const int cnt = 1 << lev;
        const int off = cnt - 1;
#pragma unroll
        for (int i = N_LEAF - 1; i >= 0; i--) {
            if (i < cnt) {
                float pr   = p[off + i];
                float base = prob[i];
                prob[2 * i]     = base * (1.f - pr);
                prob[2 * i + 1] = base * pr;
            }
        }
    }
    float acc = 0.f;
#pragma unroll
    for (int l = 0; l < N_LEAF; l++)
        acc = fmaf(prob[l], yl[(size_t)l * BATCH + b] + b2[l], acc);
    out[b] = acc;
}

// ---------------------------------------------------------------------------
extern "C" void kernel_launch(void* const* d_in, const int* in_sizes, int n_in,
                              void* d_out, int out_size)
{
    const float* x       = (const float*)d_in[0];
    const float* enc_W   = (const float*)d_in[1];
    const float* enc_b   = (const float*)d_in[2];
    const float* in_W1   = (const float*)d_in[3];
    const float* in_b1   = (const float*)d_in[4];
    const float* in_Ww   = (const float*)d_in[5];
    const float* in_bw   = (const float*)d_in[6];
    const float* in_Wb   = (const float*)d_in[7];
    const float* in_bb   = (const float*)d_in[8];
    const float* in_Wbt  = (const float*)d_in[9];
    const float* in_bbt  = (const float*)d_in[10];
    const float* lf_W1   = (const float*)d_in[11];
    const float* lf_b1   = (const float*)d_in[12];
    const float* lf_W2   = (const float*)d_in[13];
    const float* lf_b2   = (const float*)d_in[14];
    float* out = (float*)d_out;

    float *pR, *yl;
    __half *xh, *xl, *e0h, *e0l, *e1h, *e1l, *wte;
    __half *ef, *lwh, *w1h, *wwh;
    cudaGetSymbolAddress((void**)&pR,  g_pR);
    cudaGetSymbolAddress((void**)&yl,  g_yleaf);
    cudaGetSymbolAddress((void**)&xh,  g_xh);
    cudaGetSymbolAddress((void**)&xl,  g_xl);
    cudaGetSymbolAddress((void**)&e0h, g_e0h);
    cudaGetSymbolAddress((void**)&e0l, g_e0l);
    cudaGetSymbolAddress((void**)&e1h, g_e1h);
    cudaGetSymbolAddress((void**)&e1l, g_e1l);
    cudaGetSymbolAddress((void**)&wte, g_wte);
    cudaGetSymbolAddress((void**)&ef,  g_ef);
    cudaGetSymbolAddress((void**)&lwh, g_lwh);
    cudaGetSymbolAddress((void**)&w1h, g_w1h);
    cudaGetSymbolAddress((void**)&wwh, g_wwh);

    cudaFuncSetAttribute(enc_kernel<0>, cudaFuncAttributeMaxDynamicSharedMemorySize, ENC_SMEM);
    cudaFuncSetAttribute(enc_kernel<1>, cudaFuncAttributeMaxDynamicSharedMemorySize, ENC_SMEM);
    cudaFuncSetAttribute(tail_kernel,   cudaFuncAttributeMaxDynamicSharedMemorySize, TAIL_SMEM);

    // 1) all prep in one launch
    prep_all_kernel<<<PR_WTL, 256>>>(x, xh, xl, in_W1, w1h,
                                     in_Ww, wwh, yl,
                                     enc_W, wte, lf_W1, lwh);

    // 2-5) encoder (M=64 x N=64 tiles, grid 512, occ 3)
    enc_kernel<0><<<dim3(128, 4), 256, ENC_SMEM>>>(xh, xl, wte,
        enc_b, e0h, e0l, nullptr);
    enc_kernel<0><<<dim3(128, 4), 256, ENC_SMEM>>>(e0h, e0l, wte + 65536,
        enc_b + 256, e1h, e1l, nullptr);
    enc_kernel<0><<<dim3(128, 4), 256, ENC_SMEM>>>(e1h, e1l, wte + 2 * 65536,
        enc_b + 512, e0h, e0l, nullptr);
    enc_kernel<1><<<dim3(128, 4), 256, ENC_SMEM>>>(e0h, e0l, wte + 3 * 65536,
        enc_b + 768, nullptr, nullptr, ef);

    // 6) merged inner + leaf (fp16 single x single)
    tail_kernel<<<dim3(63, 128), 256, TAIL_SMEM>>>(
        ef,
        w1h, wwh, x, in_b1, in_bw, in_Wb, in_bb, in_Wbt, in_bbt, pR,
        lwh, lf_b1, lf_W2, yl);

    // 7) combine
    combine_kernel<<<BATCH / 256, 256>>>(pR, yl, lf_b2, out);
}

// round 17
// speedup vs baseline: 1.0050x; 1.0050x over previous
#include <cuda_runtime.h>
#include <cuda_bf16.h>
#include <cuda_fp16.h>
#include <cstdint>
#include <math.h>

#define BATCH 8192
#define EDIM  256
#define HDIM  50
#define N_INNER 31
#define N_LEAF  32

// ---------------------------------------------------------------------------
// Device scratch
// ---------------------------------------------------------------------------
__device__ float g_pR[N_INNER * BATCH];
__device__ float g_yleaf[N_LEAF * BATCH];

__device__ __half g_xh[BATCH * EDIM];      // x fp16 hi
__device__ __half g_xl[BATCH * EDIM];      // x fp16 lo
__device__ __half g_e0h[BATCH * EDIM];
__device__ __half g_e0l[BATCH * EDIM];
__device__ __half g_e1h[BATCH * EDIM];
__device__ __half g_e1l[BATCH * EDIM];
__device__ __half g_ef[BATCH * EDIM];      // final emb, fp16 single
// encoder weights transposed [4][N=256][K=256] fp16 single
__device__ __half g_wte[4 * 65536];
// leaf weights transposed [32][N=256][K=256] fp16 single
__device__ __half g_lwh[N_LEAF * 65536];
// inner W1 transposed [31][64][256] fp16 single, Ww transposed [31][256][64]
__device__ __half g_w1h[N_INNER * 64 * 256];
__device__ __half g_wwh[N_INNER * 256 * 64];

// ---------------------------------------------------------------------------
// Helpers
// ---------------------------------------------------------------------------
__device__ __forceinline__ uint32_t smem_u32(const void* p) {
    uint32_t a;
    asm("{ .reg .u64 t; cvta.to.shared.u64 t, %1; cvt.u32.u64 %0, t; }" : "=r"(a) : "l"(p));
    return a;
}
#define CP_ASYNC16(dst, src) \
    asm volatile("cp.async.cg.shared.global [%0], [%1], 16;" :: "r"(dst), "l"(src) : "memory")
#define CP_COMMIT() asm volatile("cp.async.commit_group;" ::: "memory")
#define CP_WAIT1()  asm volatile("cp.async.wait_group 1;" ::: "memory")
#define CP_WAIT0()  asm volatile("cp.async.wait_group 0;" ::: "memory")

#define LDSM4(r, addr) \
    asm volatile("ldmatrix.sync.aligned.m8n8.x4.shared.b16 {%0,%1,%2,%3}, [%4];" \
        : "=r"((r)[0]), "=r"((r)[1]), "=r"((r)[2]), "=r"((r)[3]) : "r"(addr))

__device__ __forceinline__ void mma_f16(float* c, const uint32_t* a, const uint32_t* b) {
    asm volatile(
        "mma.sync.aligned.m16n8k16.row.col.f32.f16.f16.f32 "
        "{%0,%1,%2,%3}, {%4,%5,%6,%7}, {%8,%9}, {%0,%1,%2,%3};"
        : "+f"(c[0]), "+f"(c[1]), "+f"(c[2]), "+f"(c[3])
        : "r"(a[0]), "r"(a[1]), "r"(a[2]), "r"(a[3]), "r"(b[0]), "r"(b[1]));
}

// fp16 hi/lo split of a pair of floats
__device__ __forceinline__ void split2h(float a, float b, uint32_t& hi, uint32_t& lo) {
    __half h0 = __float2half(a), h1 = __float2half(b);
    __half l0 = __float2half(a - __half2float(h0));
    __half l1 = __float2half(b - __half2float(h1));
    __half hh[2] = {h0, h1}, ll[2] = {l0, l1};
    hi = *(uint32_t*)hh;
    lo = *(uint32_t*)ll;
}

// ---------------------------------------------------------------------------
// Mega-prep. Regions by blockIdx.x:
// x split fp16 | W1 fp16 | Ww fp16 | zero yl |
// enc-W transpose fp16 (4x64) | leaf-W transpose fp16 (32x64)
// ---------------------------------------------------------------------------
#define PR_X   2048
#define PR_W1  (PR_X + 1984)
#define PR_WW  (PR_W1 + 1984)
#define PR_Z   (PR_WW + 256)
#define PR_WTE (PR_Z + 4 * 64)
#define PR_WTL (PR_WTE + 32 * 64)

__global__ __launch_bounds__(256) void prep_all_kernel(
    const float* __restrict__ x, __half* __restrict__ xh,
    __half* __restrict__ xl,
    const float* __restrict__ W1, __half* __restrict__ w1h,
    const float* __restrict__ Ww, __half* __restrict__ wwh,
    float* __restrict__ yl,
    const float* __restrict__ encW, __half* __restrict__ wte,
    const float* __restrict__ lfW, __half* __restrict__ lwh)
{
    const int bid = blockIdx.x;
    const int t = threadIdx.x;
    if (bid < PR_X) {
        int i = bid * 256 + t;
        float4 v = ((const float4*)x)[i];
        float f[4] = {v.x, v.y, v.z, v.w};
        __half h[4], l[4];
#pragma unroll
        for (int j = 0; j < 4; j++) {
            h[j] = __float2half(f[j]);
            l[j] = __float2half(f[j] - __half2float(h[j]));
        }
        *(uint2*)(xh + 4 * (size_t)i) = *(uint2*)h;
        *(uint2*)(xl + 4 * (size_t)i) = *(uint2*)l;
    } else if (bid < PR_W1) {
        int idx = (bid - PR_X) * 256 + t;
        int k = idx & 255, j = (idx >> 8) & 63, n = idx >> 14;
        float v = (j < HDIM) ? W1[((size_t)n * 256 + k) * HDIM + j] : 0.f;
        w1h[idx] = __float2half(v);
    } else if (bid < PR_WW) {
        int idx = (bid - PR_W1) * 256 + t;
        int j = idx & 63, d = (idx >> 6) & 255, n = idx >> 14;
        float v = (j < HDIM) ? Ww[((size_t)n * HDIM + j) * 256 + d] : 0.f;
        wwh[idx] = __float2half(v);
    } else if (bid < PR_Z) {
        int i = (bid - PR_WW) * 256 + t;
        ((float4*)yl)[i] = make_float4(0.f, 0.f, 0.f, 0.f);
    } else if (bid < PR_WTE) {
        __shared__ float tt[32][33];
        const int rel = bid - PR_Z;
        const int mat = rel >> 6;
        const int sub = rel & 63;
        const int nb = (sub & 7) * 32, kb = (sub >> 3) * 32;
        const int tx = t & 31, ty = t >> 5;
        const float* src = encW + (size_t)mat * 65536;
#pragma unroll
        for (int i = 0; i < 4; i++)
            tt[ty + 8 * i][tx] = src[(size_t)(kb + ty + 8 * i) * 256 + nb + tx];
        __syncthreads();
#pragma unroll
        for (int i = 0; i < 4; i++) {
            float v = tt[tx][ty + 8 * i];
            size_t idx = (size_t)mat * 65536 + (size_t)(nb + ty + 8 * i) * 256 + kb + tx;
            wte[idx] = __float2half(v);
        }
    } else {
        __shared__ float tt[32][33];
        const int rel = bid - PR_WTE;
        const int mat = rel >> 6;
        const int sub = rel & 63;
        const int nb = (sub & 7) * 32, kb = (sub >> 3) * 32;
        const int tx = t & 31, ty = t >> 5;
        const float* src = lfW + (size_t)mat * 65536;
#pragma unroll
        for (int i = 0; i < 4; i++)
            tt[ty + 8 * i][tx] = src[(size_t)(kb + ty + 8 * i) * 256 + nb + tx];
        __syncthreads();
#pragma unroll
        for (int i = 0; i < 4; i++) {
            float v = tt[tx][ty + 8 * i];
            size_t idx = (size_t)mat * 65536 + (size_t)(nb + ty + 8 * i) * 256 + kb + tx;
            lwh[idx] = __float2half(v);
        }
    }
}

// ---------------------------------------------------------------------------
// Encoder GEMM: fp16, activation hi/lo x weight single (2 MMA/k-step).
// M=64, N=128, BK=64, **3 stages** (prefetch depth 2 stays disjoint from the
// consuming stage) -> 4 barriers/layer. Row stride 144B. 256 thr.
// MODE 0: emit fp16 hi/lo.  MODE 1 (L4): emit fp16 single.
// ---------------------------------------------------------------------------
#define E_AL 9216                    // A-lo offset (64 x 144)
#define E_B  18432                   // B offset
#define E_SZ 36864                   // stage: A-hi + A-lo + B(128x144)
#define ENC_SMEM (3 * E_SZ)

template <int MODE>
__global__ __launch_bounds__(256, 2) void enc_kernel(
    const __half* __restrict__ Ah, const __half* __restrict__ Al,
    const __half* __restrict__ B,
    const float* __restrict__ bias,
    __half* __restrict__ oh, __half* __restrict__ ol,
    __half* __restrict__ ef)
{
    extern __shared__ char smem[];
    const uint32_t sbase = smem_u32(smem);
    const int tid = threadIdx.x;
    const int lane = tid & 31, warp = tid >> 5;
    const int m0 = blockIdx.x * 64;
    const int n0 = blockIdx.y * 128;
    const int wm = (warp >> 2) * 32;   // {0,32}
    const int wn = (warp & 3) * 32;    // {0,32,64,96}

    float c[2][4][4];
#pragma unroll
    for (int mf = 0; mf < 2; mf++)
#pragma unroll
        for (int nf = 0; nf < 4; nf++)
#pragma unroll
            for (int q = 0; q < 4; q++) c[mf][nf][q] = 0.f;

    const int arow = (lane & 7) + ((lane >> 3) & 1) * 8;
    const int acol = (lane >> 4) * 8;
    const int brow = (lane & 7) + (lane >> 4) * 8;
    const int bcol = ((lane >> 3) & 1) * 8;

#define E_ISSUE(CI) do {                                                        \
    const int k0_ = (CI) * 64;                                                  \
    const uint32_t st_ = sbase + ((CI) % 3) * E_SZ;                             \
    /* A: thread -> row tid>>2, units (tid&3) and (tid&3)+4 */                  \
    const uint32_t da = st_ + (tid >> 2) * 144 + (tid & 3) * 16;                \
    const size_t ga = (size_t)(m0 + (tid >> 2)) * 256 + k0_ + (tid & 3) * 8;    \
    CP_ASYNC16(da,             Ah + ga);                                        \
    CP_ASYNC16(da + 64,        Ah + ga + 32);                                   \
    CP_ASYNC16(da + E_AL,      Al + ga);                                        \
    CP_ASYNC16(da + E_AL + 64, Al + ga + 32);                                   \
    /* B: thread -> row tid>>1, half (tid&1), 4 units */                        \
    const uint32_t db = st_ + E_B + (tid >> 1) * 144 + (tid & 1) * 64;          \
    const size_t gb = (size_t)(n0 + (tid >> 1)) * 256 + k0_ + (tid & 1) * 32;   \
    CP_ASYNC16(db,      B + gb);                                                \
    CP_ASYNC16(db + 16, B + gb + 8);                                            \
    CP_ASYNC16(db + 32, B + gb + 16);                                           \
    CP_ASYNC16(db + 48, B + gb + 24);                                           \
    CP_COMMIT();                                                                \
} while (0)

    E_ISSUE(0);
    E_ISSUE(1);

#pragma unroll 1
    for (int ci = 0; ci < 4; ci++) {
        if (ci < 3) CP_WAIT1(); else CP_WAIT0();
        __syncthreads();
        if (ci < 2) E_ISSUE(ci + 2);

        const uint32_t st = sbase + (ci % 3) * E_SZ;
#pragma unroll
        for (int kk = 0; kk < 64; kk += 16) {
            uint32_t ah[2][4], al[2][4];
#pragma unroll
            for (int mf = 0; mf < 2; mf++) {
                uint32_t addr = st + (wm + mf * 16 + arow) * 144 + (kk + acol) * 2;
                LDSM4(ah[mf], addr);
                LDSM4(al[mf], addr + E_AL);
            }
            uint32_t bf[4][2];
#pragma unroll
            for (int np = 0; np < 2; np++) {
                uint32_t r[4];
                LDSM4(r, st + E_B + (wn + np * 16 + brow) * 144 + (kk + bcol) * 2);
                bf[2 * np][0] = r[0]; bf[2 * np][1] = r[1];
                bf[2 * np + 1][0] = r[2]; bf[2 * np + 1][1] = r[3];
            }
#pragma unroll
            for (int mf = 0; mf < 2; mf++)
#pragma unroll
                for (int nf = 0; nf < 4; nf++) {
                    mma_f16(c[mf][nf], ah[mf], bf[nf]);
                    mma_f16(c[mf][nf], al[mf], bf[nf]);
                }
        }
    }
#undef E_ISSUE

    const int erow = lane >> 2;
    const int ecol = (lane & 3) * 2;
#pragma unroll
    for (int mf = 0; mf < 2; mf++) {
        const int gr0 = m0 + wm + mf * 16 + erow;
#pragma unroll
        for (int nf = 0; nf < 4; nf++) {
            const int gc = n0 + wn + nf * 8 + ecol;
            float2 bb = *(const float2*)&bias[gc];
            float v00 = fmaxf(c[mf][nf][0] + bb.x, 0.f);
            float v01 = fmaxf(c[mf][nf][1] + bb.y, 0.f);
            float v10 = fmaxf(c[mf][nf][2] + bb.x, 0.f);
            float v11 = fmaxf(c[mf][nf][3] + bb.y, 0.f);
            const size_t i0 = (size_t)gr0 * 256 + gc;
            const size_t i1 = (size_t)(gr0 + 8) * 256 + gc;
            if (MODE == 0) {
                uint32_t h0, l0, h1, l1;
                split2h(v00, v01, h0, l0);
                split2h(v10, v11, h1, l1);
                *(uint32_t*)(oh + i0) = h0;
                *(uint32_t*)(oh + i1) = h1;
                *(uint32_t*)(ol + i0) = l0;
                *(uint32_t*)(ol + i1) = l1;
            } else {
                __half p0[2] = {__float2half(v00), __float2half(v01)};
                __half p1[2] = {__float2half(v10), __float2half(v11)};
                *(uint32_t*)(ef + i0) = *(uint32_t*)p0;
                *(uint32_t*)(ef + i1) = *(uint32_t*)p1;
            }
        }
    }
}

// ---------------------------------------------------------------------------
// TAIL kernel: inner (blockIdx.x < 31) + leaf (blockIdx.x >= 31).
// Pure fp16 single x single: 1 MMA per k-step. grid (63, 128), block 256.
// (Byte-identical to round 12/13/14 — proven.)
// ---------------------------------------------------------------------------
#define IA_SZ  10240
#define IB_SZ  12288
#define IN_HF  36864
#define IN_RED 46080
#define IN_WBS 47616
#define IN_WBTS 47872
#define L_B   10240
#define L_STG 20480
#define L_SC  (3 * L_STG)
#define TAIL_SMEM (L_SC + 1024)

__global__ __launch_bounds__(256, 2) void tail_kernel(
    const __half* __restrict__ ef,
    const __half* __restrict__ w1h, const __half* __restrict__ wwh,
    const float* __restrict__ x, const float* __restrict__ b1,
    const float* __restrict__ bw, const float* __restrict__ Wb,
    const float* __restrict__ bb, const float* __restrict__ Wbt,
    const float* __restrict__ bbt, float* __restrict__ pR,
    const __half* __restrict__ Lwh,
    const float* __restrict__ lbias, const float* __restrict__ w2,
    float* __restrict__ yleaf)
{
    extern __shared__ char smem[];
    const uint32_t sb = smem_u32(smem);
    const int tid = threadIdx.x, lane = tid & 31, w = tid >> 5;

    const int arow = (lane & 7) + ((lane >> 3) & 1) * 8;
    const int acol = (lane >> 4) * 8;
    const int brow = (lane & 7) + (lane >> 4) * 8;
    const int bcol = ((lane >> 3) & 1) * 8;
    const int crow = tid >> 2, cu = tid & 3;

    if (blockIdx.x < N_INNER) {
        // ================= INNER path =================
        const int n = blockIdx.x, m0 = blockIdx.y * 64;

        float* sWb  = (float*)(smem + IN_WBS);
        float* sWbt = (float*)(smem + IN_WBTS);
        if (tid < HDIM)          sWb[tid] = Wb[n * HDIM + tid];
        else if (tid < 2 * HDIM) sWbt[tid - HDIM] = Wbt[n * HDIM + tid - HDIM];

        const __half* w1p = w1h + (size_t)n * 64 * 256;
        const __half* wwp = wwh + (size_t)n * 256 * 64;

#define IN_ISSUE(CI) do {                                           \
    const int k0_ = (CI) * 32;                                      \
    const uint32_t st_ = sb + ((CI) % 3) * IA_SZ;                   \
    const uint32_t d = st_ + crow * 80 + cu * 16;                   \
    const size_t ga = (size_t)(m0 + crow) * 256 + k0_ + cu * 8;     \
    const size_t gw = (size_t)crow * 256 + k0_ + cu * 8;            \
    CP_ASYNC16(d,        ef + ga);                                  \
    CP_ASYNC16(d + 5120, w1p + gw);                                 \
    CP_COMMIT();                                                    \
} while (0)

        const int wmA = (w >> 1) * 16, wnA = (w & 1) * 32;
        float accA[4][4];
#pragma unroll
        for (int i = 0; i < 4; i++)
#pragma unroll
            for (int q = 0; q < 4; q++) accA[i][q] = 0.f;

        IN_ISSUE(0);
        IN_ISSUE(1);

#pragma unroll 1
        for (int ci = 0; ci < 8; ci++) {
            if (ci < 7) CP_WAIT1(); else CP_WAIT0();
            __syncthreads();
            if (ci < 6) IN_ISSUE(ci + 2);

            const uint32_t st = sb + (ci % 3) * IA_SZ;
#pragma unroll
            for (int kk = 0; kk < 32; kk += 16) {
                uint32_t a[4];
                LDSM4(a, st + (wmA + arow) * 80 + (kk + acol) * 2);
                uint32_t bf[4][2];
#pragma unroll
                for (int g = 0; g < 2; g++) {
                    uint32_t r[4];
                    LDSM4(r, st + 5120 + (wnA + g * 16 + brow) * 80 + (kk + bcol) * 2);
                    bf[2 * g][0] = r[0]; bf[2 * g][1] = r[1];
                    bf[2 * g + 1][0] = r[2]; bf[2 * g + 1][1] = r[3];
                }
#pragma unroll
                for (int nf = 0; nf < 4; nf++)
                    mma_f16(accA[nf], a, bf[nf]);
            }
        }
#undef IN_ISSUE

        {
            const int r0 = wmA + (lane >> 2);
#pragma unroll
            for (int nf = 0; nf < 4; nf++) {
                const int col = wnA + nf * 8 + (lane & 3) * 2;
                const float bb0 = (col < HDIM)     ? b1[n * HDIM + col]     : 0.f;
                const float bb1 = (col + 1 < HDIM) ? b1[n * HDIM + col + 1] : 0.f;
                __half p0[2] = {__float2half(fmaxf(accA[nf][0] + bb0, 0.f)),
                                __float2half(fmaxf(accA[nf][1] + bb1, 0.f))};
                __half p1[2] = {__float2half(fmaxf(accA[nf][2] + bb0, 0.f)),
                                __float2half(fmaxf(accA[nf][3] + bb1, 0.f))};
                *(uint32_t*)(smem + IN_HF + r0 * 144 + col * 2) = *(uint32_t*)p0;
                *(uint32_t*)(smem + IN_HF + (r0 + 8) * 144 + col * 2) = *(uint32_t*)p1;
            }
        }
        __syncthreads();

#define IN_ISSUE_B(KK) do {                                         \
    const uint32_t st_ = sb + ((KK) % 3) * IB_SZ;                   \
    const uint32_t d = st_ + tid * 48;                              \
    const size_t g = (size_t)tid * 64 + (KK) * 16;                  \
    CP_ASYNC16(d,      wwp + g);                                    \
    CP_ASYNC16(d + 16, wwp + g + 8);                                \
    CP_COMMIT();                                                    \
} while (0)

        const int wmB = (w >> 1) * 16, wnB = (w & 1) * 128;
        float z[16][4];
#pragma unroll
        for (int nf = 0; nf < 16; nf++)
#pragma unroll
            for (int q = 0; q < 4; q++) z[nf][q] = 0.f;

        IN_ISSUE_B(0);
        IN_ISSUE_B(1);

#pragma unroll 1
        for (int kk = 0; kk < 4; kk++) {
            if (kk < 3) CP_WAIT1(); else CP_WAIT0();
            __syncthreads();
            if (kk < 2) IN_ISSUE_B(kk + 2);

            const uint32_t st = sb + (kk % 3) * IB_SZ;
            uint32_t a[4];
            LDSM4(a, sb + IN_HF + (wmB + arow) * 144 + (kk * 16 + acol) * 2);
#pragma unroll
            for (int g = 0; g < 8; g++) {
                uint32_t r[4];
                LDSM4(r, st + (wnB + g * 16 + brow) * 48 + bcol * 2);
                uint32_t b0[2] = {r[0], r[1]}, b1f[2] = {r[2], r[3]};
                mma_f16(z[2 * g],     a, b0);
                mma_f16(z[2 * g + 1], a, b1f);
            }
        }
#undef IN_ISSUE_B

        float* redmax = (float*)(smem + IN_RED);
        float* redse  = redmax + 128;
        float* redsx  = redse + 128;

        const int r0 = wmB + (lane >> 2), r1 = r0 + 8;
        float mx0 = -1e30f, mx1 = -1e30f;
#pragma unroll
        for (int nf = 0; nf < 16; nf++) {
            const int col = wnB + nf * 8 + (lane & 3) * 2;
            float2 bwv = *(const float2*)&bw[n * 256 + col];
            z[nf][0] += bwv.x; z[nf][1] += bwv.y;
            z[nf][2] += bwv.x; z[nf][3] += bwv.y;
            mx0 = fmaxf(mx0, fmaxf(z[nf][0], z[nf][1]));
            mx1 = fmaxf(mx1, fmaxf(z[nf][2], z[nf][3]));
        }
        mx0 = fmaxf(mx0, __shfl_xor_sync(0xffffffffu, mx0, 1));
        mx0 = fmaxf(mx0, __shfl_xor_sync(0xffffffffu, mx0, 2));
        mx1 = fmaxf(mx1, __shfl_xor_sync(0xffffffffu, mx1, 1));
        mx1 = fmaxf(mx1, __shfl_xor_sync(0xffffffffu, mx1, 2));
        if ((lane & 3) == 0) {
            redmax[(w & 1) * 64 + r0] = mx0;
            redmax[(w & 1) * 64 + r1] = mx1;
        }
        __syncthreads();
        mx0 = fmaxf(redmax[r0], redmax[64 + r0]);
        mx1 = fmaxf(redmax[r1], redmax[64 + r1]);

        float se0 = 0.f, sx0 = 0.f, se1 = 0.f, sx1 = 0.f;
        const float* x0 = x + (size_t)(m0 + r0) * 256;
        const float* x1 = x + (size_t)(m0 + r1) * 256;
#pragma unroll
        for (int nf = 0; nf < 16; nf++) {
            const int col = wnB + nf * 8 + (lane & 3) * 2;
            float2 xv0 = *(const float2*)&x0[col];
            float2 xv1 = *(const float2*)&x1[col];
            float e;
            e = __expf(z[nf][0] - mx0); se0 += e; sx0 = fmaf(e, xv0.x, sx0);
            e = __expf(z[nf][1] - mx0); se0 += e; sx0 = fmaf(e, xv0.y, sx0);
            e = __expf(z[nf][2] - mx1); se1 += e; sx1 = fmaf(e, xv1.x, sx1);
            e = __expf(z[nf][3] - mx1); se1 += e; sx1 = fmaf(e, xv1.y, sx1);
        }
#pragma unroll
        for (int off = 1; off <= 2; off <<= 1) {
            se0 += __shfl_xor_sync(0xffffffffu, se0, off);
            sx0 += __shfl_xor_sync(0xffffffffu, sx0, off);
            se1 += __shfl_xor_sync(0xffffffffu, se1, off);
            sx1 += __shfl_xor_sync(0xffffffffu, sx1, off);
        }
        if ((lane & 3) == 0) {
            redse[(w & 1) * 64 + r0] = se0; redse[(w & 1) * 64 + r1] = se1;
            redsx[(w & 1) * 64 + r0] = sx0; redsx[(w & 1) * 64 + r1] = sx1;
        }
        __syncthreads();

        if ((w & 1) == 0) {
            float pb0 = 0.f, pbt0 = 0.f, pb1 = 0.f, pbt1 = 0.f;
            for (int j = (lane & 3); j < HDIM; j += 4) {
                float h0 = __half2float(*(const __half*)(smem + IN_HF + r0 * 144 + j * 2));
                float h1 = __half2float(*(const __half*)(smem + IN_HF + r1 * 144 + j * 2));
                pb0  = fmaf(h0, sWb[j],  pb0);
                pbt0 = fmaf(h0, sWbt[j], pbt0);
                pb1  = fmaf(h1, sWb[j],  pb1);
                pbt1 = fmaf(h1, sWbt[j], pbt1);
            }
#pragma unroll
            for (int off = 1; off <= 2; off <<= 1) {
                pb0  += __shfl_xor_sync(0xffffffffu, pb0, off);
                pbt0 += __shfl_xor_sync(0xffffffffu, pbt0, off);
                pb1  += __shfl_xor_sync(0xffffffffu, pb1, off);
                pbt1 += __shfl_xor_sync(0xffffffffu, pbt1, off);
            }
            if ((lane & 3) == 0) {
                const float bbn = bb[n], bbtn = bbt[n];
                float seA = redse[r0] + redse[64 + r0];
                float sxA = redsx[r0] + redsx[64 + r0];
                float val = (pbt0 + bbtn) * (sxA / seA + pb0 + bbn);
                pR[(size_t)n * BATCH + m0 + r0] = 1.f / (1.f + __expf(-val));
                seA = redse[r1] + redse[64 + r1];
                sxA = redsx[r1] + redsx[64 + r1];
                val = (pbt1 + bbtn) * (sxA / seA + pb1 + bbn);
                pR[(size_t)n * BATCH + m0 + r1] = 1.f / (1.f + __expf(-val));
            }
        }
    } else {
        // ================= LEAF path =================
        const int mat = blockIdx.x - N_INNER;
        const int m0 = (blockIdx.y >> 1) * 128;
        const int n0 = (blockIdx.y & 1) * 128;
        const int wm = (w >> 1) * 32;
        const int wn = (w & 1) * 64;

        const __half* bp = Lwh + (size_t)mat * 65536;

        float* s_bias = (float*)(smem + L_SC);
        float* s_w2   = (float*)(smem + L_SC + 512);
        if (tid < 128) {
            s_bias[tid] = lbias[(size_t)mat * 256 + n0 + tid];
            s_w2[tid]   = w2[(size_t)mat * 256 + n0 + tid];
        }

        float c[2][8][4];
#pragma unroll
        for (int mf = 0; mf < 2; mf++)
#pragma unroll
            for (int nf = 0; nf < 8; nf++)
#pragma unroll
                for (int q = 0; q < 4; q++) c[mf][nf][q] = 0.f;

#define L_ISSUE(CI) do {                                                        \
    const int k0_ = (CI) * 32;                                                  \
    const uint32_t st_ = sb + ((CI) % 3) * L_STG;                               \
    const uint32_t d0 = st_ + crow * 80 + cu * 16;                              \
    const uint32_t d1 = st_ + (crow + 64) * 80 + cu * 16;                       \
    const size_t ga = (size_t)(m0 + crow) * 256 + k0_ + cu * 8;                 \
    const size_t gb = (size_t)(n0 + crow) * 256 + k0_ + cu * 8;                 \
    CP_ASYNC16(d0,        ef + ga);                                             \
    CP_ASYNC16(d1,        ef + ga + 64 * 256);                                  \
    CP_ASYNC16(d0 + L_B,  bp + gb);                                             \
    CP_ASYNC16(d1 + L_B,  bp + gb + 64 * 256);                                  \
    CP_COMMIT();                                                                \
} while (0)

        L_ISSUE(0);
        L_ISSUE(1);

#pragma unroll 1
        for (int ci = 0; ci < 8; ci++) {
            if (ci < 7) CP_WAIT1(); else CP_WAIT0();
            __syncthreads();
            if (ci < 6) L_ISSUE(ci + 2);

            const uint32_t st = sb + (ci % 3) * L_STG;
#pragma unroll
            for (int kk = 0; kk < 32; kk += 16) {
                uint32_t a[2][4];
#pragma unroll
                for (int mf = 0; mf < 2; mf++)
                    LDSM4(a[mf], st + (wm + mf * 16 + arow) * 80 + (kk + acol) * 2);
                uint32_t bf[8][2];
#pragma unroll
                for (int np = 0; np < 4; np++) {
                    uint32_t r[4];
                    LDSM4(r, st + L_B + (wn + np * 16 + brow) * 80 + (kk + bcol) * 2);
                    bf[2 * np][0] = r[0]; bf[2 * np][1] = r[1];
                    bf[2 * np + 1][0] = r[2]; bf[2 * np + 1][1] = r[3];
                }
#pragma unroll
                for (int mf = 0; mf < 2; mf++)
#pragma unroll
                    for (int nf = 0; nf < 8; nf++)
                        mma_f16(c[mf][nf], a[mf], bf[nf]);
            }
        }
#undef L_ISSUE

        const int erow = lane >> 2;
        const int ecol = (lane & 3) * 2;
        float part[2][2] = {{0.f, 0.f}, {0.f, 0.f}};
#pragma unroll
        for (int mf = 0; mf < 2; mf++)
#pragma unroll
            for (int nf = 0; nf < 8; nf++) {
                const int lc = wn + nf * 8 + ecol;
                const float b0s = s_bias[lc], b1s = s_bias[lc + 1];
                const float w0 = s_w2[lc], w1 = s_w2[lc + 1];
                part[mf][0] = fmaf(fmaxf(c[mf][nf][0] + b0s, 0.f), w0, part[mf][0]);
                part[mf][0] = fmaf(fmaxf(c[mf][nf][1] + b1s, 0.f), w1, part[mf][0]);
                part[mf][1] = fmaf(fmaxf(c[mf][nf][2] + b0s, 0.f), w0, part[mf][1]);
                part[mf][1] = fmaf(fmaxf(c[mf][nf][3] + b1s, 0.f), w1, part[mf][1]);
            }
#pragma unroll
        for (int mf = 0; mf < 2; mf++)
#pragma unroll
            for (int h = 0; h < 2; h++) {
                part[mf][h] += __shfl_xor_sync(0xffffffffu, part[mf][h], 1);
                part[mf][h] += __shfl_xor_sync(0xffffffffu, part[mf][h], 2);
            }
        if ((lane & 3) == 0) {
#pragma unroll
            for (int mf = 0; mf < 2; mf++)
#pragma unroll
                for (int h = 0; h < 2; h++) {
                    const int row = m0 + wm + mf * 16 + h * 8 + erow;
                    atomicAdd(&yleaf[(size_t)mat * BATCH + row], part[mf][h]);
                }
        }
    }
}

// ---------------------------------------------------------------------------
// Combine
// ---------------------------------------------------------------------------
__global__ __launch_bounds__(256) void combine_kernel(
    const float* __restrict__ pR, const float* __restrict__ yl,
    const float* __restrict__ b2, float* __restrict__ out)
{
    const int b = blockIdx.x * 256 + threadIdx.x;
    float p[N_INNER];
#pragma unroll
    for (int i = 0; i < N_INNER; i++) p[i] = pR[(size_t)i * BATCH + b];

    float prob[N_LEAF];
    prob[0] = 1.f;
#pragma unroll
    for (int lev = 0; lev < 5; lev++) {
        const int cnt = 1 << lev;
        const int off = cnt - 1;
#pragma unroll
        for (int i = N_LEAF - 1; i >= 0; i--) {
            if (i < cnt) {
                float pr   = p[off + i];
                float base = prob[i];
                prob[2 * i]     = base * (1.f - pr);
                prob[2 * i + 1] = base * pr;
            }
        }
    }
    float acc = 0.f;
#pragma unroll
    for (int l = 0; l < N_LEAF; l++)
        acc = fmaf(prob[l], yl[(size_t)l * BATCH + b] + b2[l], acc);
    out[b] = acc;
}

// ---------------------------------------------------------------------------
extern "C" void kernel_launch(void* const* d_in, const int* in_sizes, int n_in,
                              void* d_out, int out_size)
{
    const float* x       = (const float*)d_in[0];
    const float* enc_W   = (const float*)d_in[1];
    const float* enc_b   = (const float*)d_in[2];
    const float* in_W1   = (const float*)d_in[3];
    const float* in_b1   = (const float*)d_in[4];
    const float* in_Ww   = (const float*)d_in[5];
    const float* in_bw   = (const float*)d_in[6];
    const float* in_Wb   = (const float*)d_in[7];
    const float* in_bb   = (const float*)d_in[8];
    const float* in_Wbt  = (const float*)d_in[9];
    const float* in_bbt  = (const float*)d_in[10];
    const float* lf_W1   = (const float*)d_in[11];
    const float* lf_b1   = (const float*)d_in[12];
    const float* lf_W2   = (const float*)d_in[13];
    const float* lf_b2   = (const float*)d_in[14];
    float* out = (float*)d_out;

    float *pR, *yl;
    __half *xh, *xl, *e0h, *e0l, *e1h, *e1l, *wte;
    __half *ef, *lwh, *w1h, *wwh;
    cudaGetSymbolAddress((void**)&pR,  g_pR);
    cudaGetSymbolAddress((void**)&yl,  g_yleaf);
    cudaGetSymbolAddress((void**)&xh,  g_xh);
    cudaGetSymbolAddress((void**)&xl,  g_xl);
    cudaGetSymbolAddress((void**)&e0h, g_e0h);
    cudaGetSymbolAddress((void**)&e0l, g_e0l);
    cudaGetSymbolAddress((void**)&e1h, g_e1h);
    cudaGetSymbolAddress((void**)&e1l, g_e1l);
    cudaGetSymbolAddress((void**)&wte, g_wte);
    cudaGetSymbolAddress((void**)&ef,  g_ef);
    cudaGetSymbolAddress((void**)&lwh, g_lwh);
    cudaGetSymbolAddress((void**)&w1h, g_w1h);
    cudaGetSymbolAddress((void**)&wwh, g_wwh);

    cudaFuncSetAttribute(enc_kernel<0>, cudaFuncAttributeMaxDynamicSharedMemorySize, ENC_SMEM);
    cudaFuncSetAttribute(enc_kernel<1>, cudaFuncAttributeMaxDynamicSharedMemorySize, ENC_SMEM);
    cudaFuncSetAttribute(tail_kernel,   cudaFuncAttributeMaxDynamicSharedMemorySize, TAIL_SMEM);

    // 1) all prep in one launch
    prep_all_kernel<<<PR_WTL, 256>>>(x, xh, xl, in_W1, w1h,
                                     in_Ww, wwh, yl,
                                     enc_W, wte, lf_W1, lwh);

    // 2-5) encoder (M=64 x N=128, BK=64, 3-stage: 4 barriers/layer)
    enc_kernel<0><<<dim3(128, 2), 256, ENC_SMEM>>>(xh, xl, wte,
        enc_b, e0h, e0l, nullptr);
    enc_kernel<0><<<dim3(128, 2), 256, ENC_SMEM>>>(e0h, e0l, wte + 65536,
        enc_b + 256, e1h, e1l, nullptr);
    enc_kernel<0><<<dim3(128, 2), 256, ENC_SMEM>>>(e1h, e1l, wte + 2 * 65536,
        enc_b + 512, e0h, e0l, nullptr);
    enc_kernel<1><<<dim3(128, 2), 256, ENC_SMEM>>>(e0h, e0l, wte + 3 * 65536,
        enc_b + 768, nullptr, nullptr, ef);

    // 6) merged inner + leaf (fp16 single x single)
    tail_kernel<<<dim3(63, 128), 256, TAIL_SMEM>>>(
        ef,
        w1h, wwh, x, in_b1, in_bw, in_Wb, in_bb, in_Wbt, in_bbt, pR,
        lwh, lf_b1, lf_W2, yl);

    // 7) combine
    combine_kernel<<<BATCH / 256, 256>>>(pR, yl, lf_b2, out);
}